// round 1
// baseline (speedup 1.0000x reference)
#include <cuda_runtime.h>
#include <math.h>

#define Nn 100000
#define Ee 1600000
#define Ff 128
#define NFf 4
#define Dd 64
#define NLl 3
#define Gg 128

// ---------------- device scratch (no allocations allowed) ----------------
__device__ int   g_deg[Nn];
__device__ int   g_rowptr[Nn + 1];
__device__ int   g_fill[Nn];
__device__ int   g_bsums[256];
__device__ int   g_srcs[Ee];
__device__ int   g_eids[Ee];
__device__ float g_wcsr[NFf * Ee];
__device__ float g_stateA[Nn * Dd];
__device__ float g_stateB[Nn * Dd];
__device__ int   g_gcnt[Gg];
__device__ int   g_gstart[Gg + 1];

// ---------------- CSR build ----------------
__global__ void k_zero() {
    int i = blockIdx.x * blockDim.x + threadIdx.x;
    if (i < Nn) g_deg[i] = 0;
    if (i < Gg) g_gcnt[i] = 0;
}

__global__ void k_hist(const int* __restrict__ dst, const int* __restrict__ batch) {
    int i = blockIdx.x * blockDim.x + threadIdx.x;
    if (i < Ee) atomicAdd(&g_deg[dst[i]], 1);
    if (i < Nn) atomicAdd(&g_gcnt[batch[i]], 1);
}

__global__ void k_scan1() {
    __shared__ int tmp[1024];
    int i = blockIdx.x * 1024 + threadIdx.x;
    int v = (i < Nn) ? g_deg[i] : 0;
    tmp[threadIdx.x] = v;
    __syncthreads();
    for (int off = 1; off < 1024; off <<= 1) {
        int t = 0;
        if (threadIdx.x >= off) t = tmp[threadIdx.x - off];
        __syncthreads();
        if (threadIdx.x >= off) tmp[threadIdx.x] += t;
        __syncthreads();
    }
    if (i < Nn) g_rowptr[i + 1] = tmp[threadIdx.x];
    if (threadIdx.x == 1023) g_bsums[blockIdx.x] = tmp[1023];
}

__global__ void k_scan2(int nb) {
    if (threadIdx.x == 0 && blockIdx.x == 0) {
        int run = 0;
        for (int b = 0; b < nb; b++) { int v = g_bsums[b]; g_bsums[b] = run; run += v; }
    }
}

__global__ void k_scan3() {
    int i = blockIdx.x * 1024 + threadIdx.x;
    if (i < Nn) {
        int v = g_rowptr[i + 1] + g_bsums[blockIdx.x];
        g_rowptr[i + 1] = v;
        if (i + 1 < Nn) g_fill[i + 1] = v;
    }
    if (i == 0) { g_rowptr[0] = 0; g_fill[0] = 0; }
}

__global__ void k_scatter(const int* __restrict__ src, const int* __restrict__ dst) {
    int e = blockIdx.x * blockDim.x + threadIdx.x;
    if (e < Ee) {
        int d = dst[e];
        int p = atomicAdd(&g_fill[d], 1);
        g_srcs[p] = src[e];
        g_eids[p] = e;
    }
}

// deterministic per-node edge order (sorted by original edge id)
__global__ void k_sortseg() {
    int n = blockIdx.x * blockDim.x + threadIdx.x;
    if (n >= Nn) return;
    int b = g_rowptr[n], e = g_rowptr[n + 1];
    for (int i = b + 1; i < e; i++) {
        int ke = g_eids[i], ks = g_srcs[i];
        int j = i - 1;
        while (j >= b && g_eids[j] > ke) {
            g_eids[j + 1] = g_eids[j];
            g_srcs[j + 1] = g_srcs[j];
            j--;
        }
        g_eids[j + 1] = ke;
        g_srcs[j + 1] = ks;
    }
}

__global__ void k_buildw(const float* __restrict__ att) {
    int j = blockIdx.x * blockDim.x + threadIdx.x;
    if (j < Ee) {
        int e = g_eids[j];
#pragma unroll
        for (int f = 0; f < NFf; f++) g_wcsr[f * Ee + j] = att[f * Ee + e];
    }
}

__global__ void k_gscan() {
    if (threadIdx.x == 0 && blockIdx.x == 0) {
        int run = 0;
        for (int g = 0; g < Gg; g++) { g_gstart[g] = run; run += g_gcnt[g]; }
        g_gstart[Gg] = run;
    }
}

// ---------------- lin: out0 = x @ lin_W[f] + lin_b[f] ----------------
__global__ __launch_bounds__(512) void k_lin(const float* __restrict__ x,
                                             const float* __restrict__ W,
                                             const float* __restrict__ b,
                                             float* __restrict__ out) {
    __shared__ float sW[Ff * Dd];
    __shared__ float sb[Dd];
    __shared__ float sX[16][Ff];
    int tid = threadIdx.x;
    for (int i = tid; i < Ff * Dd; i += 512) sW[i] = W[i];
    if (tid < Dd) sb[tid] = b[tid];
    __syncthreads();
    int warp = tid >> 5, lane = tid & 31, d0 = lane * 2;
    int gw = blockIdx.x * 16 + warp;
    int nw = gridDim.x * 16;
    for (int n = gw; n < Nn; n += nw) {
#pragma unroll
        for (int t = 0; t < 4; t++) sX[warp][lane + 32 * t] = x[n * Ff + lane + 32 * t];
        __syncwarp();
        float a0 = sb[d0], a1 = sb[d0 + 1];
#pragma unroll 8
        for (int k = 0; k < Ff; k++) {
            float xk = sX[warp][k];
            float2 w2 = *(const float2*)(sW + k * Dd + d0);
            a0 += xk * w2.x;
            a1 += xk * w2.y;
        }
        *(float2*)(out + n * Dd + d0) = make_float2(a0, a1);
        __syncwarp();
    }
}

// ---------------- fused layer: agg -> GraphConv(relu) -> GRU ----------------
__device__ __forceinline__ float sigm(float v) { return 1.f / (1.f + expf(-v)); }

__global__ __launch_bounds__(512) void k_layer(const float* __restrict__ in_state,
                                               float* __restrict__ out_state,
                                               const float* __restrict__ Wrel,
                                               const float* __restrict__ brel,
                                               const float* __restrict__ Wroot,
                                               const float* __restrict__ Wih,
                                               const float* __restrict__ Whh,
                                               const float* __restrict__ bih,
                                               const float* __restrict__ bhh,
                                               const float* __restrict__ wf) {
    extern __shared__ float sh[];
    float* sWrel  = sh;                 // 4096  [k][d]
    float* sWroot = sWrel + 4096;       // 4096  [k][d]
    float* sWihT  = sWroot + 4096;      // 12288 [k][j] j<192
    float* sWhhT  = sWihT + 12288;      // 12288
    float* sbrel  = sWhhT + 12288;      // 64
    float* sbih   = sbrel + 64;         // 192
    float* sbhh   = sbih + 192;         // 192
    float* sStage = sbhh + 192;         // 16 warps * 192

    int tid = threadIdx.x;
    for (int i = tid; i < 4096; i += 512) { sWrel[i] = Wrel[i]; sWroot[i] = Wroot[i]; }
    for (int i = tid; i < 12288; i += 512) {
        int j = i >> 6, k = i & 63;
        sWihT[k * 192 + j] = Wih[i];
        sWhhT[k * 192 + j] = Whh[i];
    }
    if (tid < 64) sbrel[tid] = brel[tid];
    if (tid < 192) { sbih[tid] = bih[tid]; sbhh[tid] = bhh[tid]; }
    __syncthreads();

    int warp = tid >> 5, lane = tid & 31, d0 = lane * 2;
    float* st   = sStage + warp * 192;
    float* sAgg = st;
    float* sIn  = st + 64;
    float* sM   = st + 128;

    int gw = blockIdx.x * 16 + warp;
    int nw = gridDim.x * 16;

    for (int n = gw; n < Nn; n += nw) {
        float2 hv = *(const float2*)(in_state + n * Dd + d0);
        sIn[d0] = hv.x; sIn[d0 + 1] = hv.y;
        // edge aggregation (CSR gather, no atomics)
        float a0 = 0.f, a1 = 0.f;
        int beg = g_rowptr[n], end = g_rowptr[n + 1];
        for (int j = beg; j < end; ++j) {
            int s = g_srcs[j];
            float w = wf[j];
            float2 xv = *(const float2*)(in_state + s * Dd + d0);
            a0 += w * xv.x;
            a1 += w * xv.y;
        }
        sAgg[d0] = a0; sAgg[d0 + 1] = a1;
        __syncwarp();
        // m = relu(agg @ Wrel + brel + h @ Wroot)
        float m0 = sbrel[d0], m1 = sbrel[d0 + 1];
#pragma unroll 8
        for (int k = 0; k < 64; ++k) {
            float ak = sAgg[k], hk = sIn[k];
            float2 wr = *(const float2*)(sWrel + k * 64 + d0);
            float2 wo = *(const float2*)(sWroot + k * 64 + d0);
            m0 += ak * wr.x + hk * wo.x;
            m1 += ak * wr.y + hk * wo.y;
        }
        m0 = fmaxf(m0, 0.f);
        m1 = fmaxf(m1, 0.f);
        sM[d0] = m0; sM[d0 + 1] = m1;
        __syncwarp();
        // GRU gates
        float gi0 = sbih[d0],       gi1 = sbih[d0 + 1];
        float gi2 = sbih[64 + d0],  gi3 = sbih[64 + d0 + 1];
        float gi4 = sbih[128 + d0], gi5 = sbih[128 + d0 + 1];
        float gh0 = sbhh[d0],       gh1 = sbhh[d0 + 1];
        float gh2 = sbhh[64 + d0],  gh3 = sbhh[64 + d0 + 1];
        float gh4 = sbhh[128 + d0], gh5 = sbhh[128 + d0 + 1];
#pragma unroll 8
        for (int k = 0; k < 64; ++k) {
            float mk = sM[k], hk = sIn[k];
            const float* wi = sWihT + k * 192;
            const float* wh = sWhhT + k * 192;
            float2 t;
            t = *(const float2*)(wi + d0);        gi0 += mk * t.x; gi1 += mk * t.y;
            t = *(const float2*)(wi + 64 + d0);   gi2 += mk * t.x; gi3 += mk * t.y;
            t = *(const float2*)(wi + 128 + d0);  gi4 += mk * t.x; gi5 += mk * t.y;
            t = *(const float2*)(wh + d0);        gh0 += hk * t.x; gh1 += hk * t.y;
            t = *(const float2*)(wh + 64 + d0);   gh2 += hk * t.x; gh3 += hk * t.y;
            t = *(const float2*)(wh + 128 + d0);  gh4 += hk * t.x; gh5 += hk * t.y;
        }
        float r0 = sigm(gi0 + gh0), r1 = sigm(gi1 + gh1);
        float z0 = sigm(gi2 + gh2), z1 = sigm(gi3 + gh3);
        float n0 = tanhf(gi4 + r0 * gh4), n1 = tanhf(gi5 + r1 * gh5);
        float o0 = (1.f - z0) * n0 + z0 * hv.x;
        float o1 = (1.f - z1) * n1 + z1 * hv.y;
        *(float2*)(out_state + n * Dd + d0) = make_float2(o0, o1);
        __syncwarp();
    }
}

// ---------------- global mean pool ----------------
__global__ void k_pool(const float* __restrict__ feats, float* __restrict__ out) {
    int g = blockIdx.x, f = blockIdx.y, d = threadIdx.x;  // blockDim = 64
    int s = g_gstart[g], e = g_gstart[g + 1];
    const float* base = feats + f * Nn * Dd;
    float s0 = 0.f, s1 = 0.f, s2 = 0.f, s3 = 0.f;
    int i = s;
    for (; i + 3 < e; i += 4) {
        s0 += base[i * Dd + d];
        s1 += base[(i + 1) * Dd + d];
        s2 += base[(i + 2) * Dd + d];
        s3 += base[(i + 3) * Dd + d];
    }
    for (; i < e; i++) s0 += base[i * Dd + d];
    float sum = (s0 + s1) + (s2 + s3);
    int cnt = e - s;
    if (cnt < 1) cnt = 1;
    out[(f * Gg + g) * Dd + d] = sum / (float)cnt;
}

// ---------------- host ----------------
extern "C" void kernel_launch(void* const* d_in, const int* in_sizes, int n_in,
                              void* d_out, int out_size) {
    const float* x     = (const float*)d_in[0];
    const int*   ei    = (const int*)d_in[1];
    const float* att   = (const float*)d_in[2];
    const int*   batch = (const int*)d_in[3];
    const float* lin_W = (const float*)d_in[4];
    const float* lin_b = (const float*)d_in[5];
    const float* Wrel  = (const float*)d_in[6];
    const float* brel  = (const float*)d_in[7];
    const float* Wroot = (const float*)d_in[8];
    const float* Wih   = (const float*)d_in[9];
    const float* Whh   = (const float*)d_in[10];
    const float* bih   = (const float*)d_in[11];
    const float* bhh   = (const float*)d_in[12];

    float* out = (float*)d_out;
    float* feats = out + NFf * Gg * Dd;
    const int* srcp = ei;
    const int* dstp = ei + Ee;

    int sm = 148;
    cudaDeviceGetAttribute(&sm, cudaDevAttrMultiProcessorCount, 0);

    const int layerShm = (4096 * 2 + 12288 * 2 + 64 + 192 + 192 + 16 * 192) * (int)sizeof(float);
    cudaFuncSetAttribute(k_layer, cudaFuncAttributeMaxDynamicSharedMemorySize, layerShm);

    void *pa, *pb, *pw;
    cudaGetSymbolAddress(&pa, g_stateA);
    cudaGetSymbolAddress(&pb, g_stateB);
    cudaGetSymbolAddress(&pw, g_wcsr);
    float* A = (float*)pa;
    float* B = (float*)pb;
    float* wcsr = (float*)pw;

    const int NB = (Nn + 1023) / 1024;

    k_zero<<<(Nn + 255) / 256, 256>>>();
    k_hist<<<(Ee + 255) / 256, 256>>>(dstp, batch);
    k_scan1<<<NB, 1024>>>();
    k_scan2<<<1, 32>>>(NB);
    k_scan3<<<NB, 1024>>>();
    k_scatter<<<(Ee + 255) / 256, 256>>>(srcp, dstp);
    k_sortseg<<<(Nn + 127) / 128, 128>>>();
    k_buildw<<<(Ee + 255) / 256, 256>>>(att);
    k_gscan<<<1, 32>>>();

    for (int f = 0; f < NFf; f++) {
        k_lin<<<2 * sm, 512>>>(x, lin_W + f * Ff * Dd, lin_b + f * Dd, A);
        float* cur = A;
        for (int l = 0; l < NLl; l++) {
            float* nxt = (l == NLl - 1) ? (feats + f * Nn * Dd) : (cur == A ? B : A);
            int wl = f * NLl + l;
            k_layer<<<sm, 512, layerShm>>>(cur, nxt,
                                           Wrel + wl * Dd * Dd, brel + wl * Dd,
                                           Wroot + wl * Dd * Dd,
                                           Wih + f * 3 * Dd * Dd, Whh + f * 3 * Dd * Dd,
                                           bih + f * 3 * Dd, bhh + f * 3 * Dd,
                                           wcsr + f * Ee);
            cur = nxt;
        }
    }
    k_pool<<<dim3(Gg, NFf), 64>>>(feats, out);
}

// round 2
// speedup vs baseline: 1.9419x; 1.9419x over previous
#include <cuda_runtime.h>
#include <math.h>

typedef unsigned long long u64;
typedef unsigned int u32;

#define Nn 100000
#define Ee 1600000
#define Ff 128
#define NFf 4
#define Dd 64
#define NLl 3
#define Gg 128

// ---------------- device scratch (no allocations allowed) ----------------
__device__ int   g_deg[Nn];
__device__ int   g_rowptr[Nn + 1];
__device__ int   g_fill[Nn];
__device__ int   g_bsums[256];
__device__ int   g_srcs[Ee];
__device__ int   g_eids[Ee];
__device__ float g_wcsr[NFf * Ee];
__device__ float g_stateA[Nn * Dd];
__device__ float g_stateB[Nn * Dd];
__device__ int   g_gcnt[Gg];
__device__ int   g_gstart[Gg + 1];

// ---------------- packed f32x2 helpers ----------------
__device__ __forceinline__ u64 ffma2(u64 a, u64 b, u64 c) {
    u64 d; asm("fma.rn.f32x2 %0,%1,%2,%3;" : "=l"(d) : "l"(a), "l"(b), "l"(c)); return d;
}
__device__ __forceinline__ u64 splat2(float v) {
    u64 d; u32 r = __float_as_uint(v);
    asm("mov.b64 %0,{%1,%2};" : "=l"(d) : "r"(r), "r"(r)); return d;
}
__device__ __forceinline__ float2 unpk(u64 v) {
    u32 lo, hi; asm("mov.b64 {%0,%1},%2;" : "=r"(lo), "=r"(hi) : "l"(v));
    return make_float2(__uint_as_float(lo), __uint_as_float(hi));
}
__device__ __forceinline__ u64 pk(float a, float b) {
    u64 d;
    asm("mov.b64 %0,{%1,%2};" : "=l"(d) : "r"(__float_as_uint(a)), "r"(__float_as_uint(b)));
    return d;
}
__device__ __forceinline__ float sigm(float v) { return 1.f / (1.f + expf(-v)); }

// ---------------- CSR build ----------------
__global__ void k_zero() {
    int i = blockIdx.x * blockDim.x + threadIdx.x;
    if (i < Nn) g_deg[i] = 0;
    if (i < Gg) g_gcnt[i] = 0;
}

__global__ void k_hist(const int* __restrict__ dst, const int* __restrict__ batch) {
    int i = blockIdx.x * blockDim.x + threadIdx.x;
    if (i < Ee) atomicAdd(&g_deg[dst[i]], 1);
    if (i < Nn) atomicAdd(&g_gcnt[batch[i]], 1);
}

__global__ void k_scan1() {
    __shared__ int tmp[1024];
    int i = blockIdx.x * 1024 + threadIdx.x;
    int v = (i < Nn) ? g_deg[i] : 0;
    tmp[threadIdx.x] = v;
    __syncthreads();
    for (int off = 1; off < 1024; off <<= 1) {
        int t = 0;
        if (threadIdx.x >= off) t = tmp[threadIdx.x - off];
        __syncthreads();
        if (threadIdx.x >= off) tmp[threadIdx.x] += t;
        __syncthreads();
    }
    if (i < Nn) g_rowptr[i + 1] = tmp[threadIdx.x];
    if (threadIdx.x == 1023) g_bsums[blockIdx.x] = tmp[1023];
}

__global__ void k_scan2(int nb) {
    if (threadIdx.x == 0 && blockIdx.x == 0) {
        int run = 0;
        for (int b = 0; b < nb; b++) { int v = g_bsums[b]; g_bsums[b] = run; run += v; }
    }
}

__global__ void k_scan3() {
    int i = blockIdx.x * 1024 + threadIdx.x;
    if (i < Nn) {
        int v = g_rowptr[i + 1] + g_bsums[blockIdx.x];
        g_rowptr[i + 1] = v;
        if (i + 1 < Nn) g_fill[i + 1] = v;
    }
    if (i == 0) { g_rowptr[0] = 0; g_fill[0] = 0; }
}

__global__ void k_scatter(const int* __restrict__ src, const int* __restrict__ dst) {
    int e = blockIdx.x * blockDim.x + threadIdx.x;
    if (e < Ee) {
        int d = dst[e];
        int p = atomicAdd(&g_fill[d], 1);
        g_srcs[p] = src[e];
        g_eids[p] = e;
    }
}

__global__ void k_sortseg() {
    int n = blockIdx.x * blockDim.x + threadIdx.x;
    if (n >= Nn) return;
    int b = g_rowptr[n], e = g_rowptr[n + 1];
    for (int i = b + 1; i < e; i++) {
        int ke = g_eids[i], ks = g_srcs[i];
        int j = i - 1;
        while (j >= b && g_eids[j] > ke) {
            g_eids[j + 1] = g_eids[j];
            g_srcs[j + 1] = g_srcs[j];
            j--;
        }
        g_eids[j + 1] = ke;
        g_srcs[j + 1] = ks;
    }
}

__global__ void k_buildw(const float* __restrict__ att) {
    int j = blockIdx.x * blockDim.x + threadIdx.x;
    if (j < Ee) {
        int e = g_eids[j];
#pragma unroll
        for (int f = 0; f < NFf; f++) g_wcsr[f * Ee + j] = att[f * Ee + e];
    }
}

__global__ void k_gscan() {
    if (threadIdx.x == 0 && blockIdx.x == 0) {
        int run = 0;
        for (int g = 0; g < Gg; g++) { g_gstart[g] = run; run += g_gcnt[g]; }
        g_gstart[Gg] = run;
    }
}

// ---------------- lin: out = x @ lin_W[f] + lin_b[f]  (8 nodes/warp, f32x2) ----------------
#define LIN_SHM ((8192 + 64 + 12 * 1280) * 4)
__global__ __launch_bounds__(384) void k_lin(const float* __restrict__ x,
                                             const float* __restrict__ W,
                                             const float* __restrict__ b,
                                             float* __restrict__ out) {
    extern __shared__ float sh[];
    float* sW = sh;            // 8192 [k][d]
    float* sb = sW + 8192;     // 64
    float* sX = sb + 64;       // 12 * 1280, per warp [k][10]
    int tid = threadIdx.x;
    for (int i = tid; i < 8192; i += 384) sW[i] = W[i];
    if (tid < 64) sb[tid] = b[tid];
    __syncthreads();
    int warp = tid >> 5, lane = tid & 31;
    int d0 = 2 * lane;
    int nt = lane >> 2, cg = lane & 3;
    float* sXw = sX + warp * 1280;
    float bc0 = sb[d0], bc1 = sb[d0 + 1];

    for (int base = blockIdx.x * 96; base < Nn; base += gridDim.x * 96) {
        int n0 = base + warp * 8;
        if (n0 >= Nn) continue;
        {
            int n = n0 + nt;
            bool v = n < Nn;
            const float4* xr = (const float4*)(x + (v ? n : 0) * Ff) + cg * 8;
#pragma unroll
            for (int q = 0; q < 8; q++) {
                float4 t = v ? xr[q] : make_float4(0, 0, 0, 0);
                int c = cg * 32 + q * 4;
                sXw[(c + 0) * 10 + nt] = t.x;
                sXw[(c + 1) * 10 + nt] = t.y;
                sXw[(c + 2) * 10 + nt] = t.z;
                sXw[(c + 3) * 10 + nt] = t.w;
            }
        }
        __syncwarp();
        u64 acc[4][2];
#pragma unroll
        for (int p = 0; p < 4; p++) { acc[p][0] = 0ull; acc[p][1] = 0ull; }
#pragma unroll 4
        for (int k = 0; k < Ff; k++) {
            float2 w = *(const float2*)(sW + k * 64 + d0);
            u64 sw0 = splat2(w.x), sw1 = splat2(w.y);
            const u64* xp = (const u64*)(sXw + k * 10);
#pragma unroll
            for (int p = 0; p < 4; p++) {
                u64 xv = xp[p];
                acc[p][0] = ffma2(xv, sw0, acc[p][0]);
                acc[p][1] = ffma2(xv, sw1, acc[p][1]);
            }
        }
#pragma unroll
        for (int p = 0; p < 4; p++) {
            float2 a0 = unpk(acc[p][0]), a1 = unpk(acc[p][1]);
            int na = n0 + 2 * p, nb = na + 1;
            if (na < Nn) *(float2*)(out + na * 64 + d0) = make_float2(a0.x + bc0, a1.x + bc1);
            if (nb < Nn) *(float2*)(out + nb * 64 + d0) = make_float2(a0.y + bc0, a1.y + bc1);
        }
        __syncwarp();
    }
}

// ---------------- fused layer (8 nodes/warp, f32x2 packed over node pairs) ----------------
#define LAYER_SHM ((4096 * 2 + 12288 * 2 + 12 * 1280) * 4)
__global__ __launch_bounds__(384) void k_layer(const float* __restrict__ in_state,
                                               float* __restrict__ out_state,
                                               const float* __restrict__ Wrel,
                                               const float* __restrict__ brel,
                                               const float* __restrict__ Wroot,
                                               const float* __restrict__ Wih,
                                               const float* __restrict__ Whh,
                                               const float* __restrict__ bih,
                                               const float* __restrict__ bhh,
                                               const float* __restrict__ wf) {
    extern __shared__ float sh[];
    float* sWrel  = sh;                  // 4096  [k][d]
    float* sWroot = sWrel + 4096;        // 4096
    float* sWihT  = sWroot + 4096;       // 12288 [k][j]
    float* sWhhT  = sWihT + 12288;       // 12288
    float* sStage = sWhhT + 12288;       // 12 warps * 1280

    int tid = threadIdx.x;
    for (int i = tid; i < 4096; i += 384) { sWrel[i] = Wrel[i]; sWroot[i] = Wroot[i]; }
    for (int i = tid; i < 12288; i += 384) {
        int j = i >> 6, k = i & 63;
        sWihT[k * 192 + j] = Wih[i];
        sWhhT[k * 192 + j] = Whh[i];
    }
    __syncthreads();

    int warp = tid >> 5, lane = tid & 31;
    int d0 = 2 * lane;
    int nt = lane >> 2, cg = lane & 3;
    float* sIn = sStage + warp * 1280;   // [col][10] stride, nodes 0..7
    float* sA  = sIn + 640;              // agg, later m

    float br0 = brel[d0], br1 = brel[d0 + 1];
    float bi_[6], bh_[6];
#pragma unroll
    for (int g = 0; g < 3; g++) {
        bi_[2 * g] = bih[64 * g + d0]; bi_[2 * g + 1] = bih[64 * g + d0 + 1];
        bh_[2 * g] = bhh[64 * g + d0]; bh_[2 * g + 1] = bhh[64 * g + d0 + 1];
    }

    for (int base = blockIdx.x * 96; base < Nn; base += gridDim.x * 96) {
        int n0 = base + warp * 8;
        if (n0 >= Nn) continue;

        // ---- stage h (sIn) + edge aggregation (sA), transposed [col][node] ----
        {
            int n = n0 + nt;
            bool v = n < Nn;
            const float4* xr = (const float4*)(in_state + (v ? n : 0) * 64) + cg * 4;
            float acc16[16];
#pragma unroll
            for (int q = 0; q < 4; q++) {
                float4 t = v ? xr[q] : make_float4(0, 0, 0, 0);
                int c = cg * 16 + q * 4;
                sIn[(c + 0) * 10 + nt] = t.x;
                sIn[(c + 1) * 10 + nt] = t.y;
                sIn[(c + 2) * 10 + nt] = t.z;
                sIn[(c + 3) * 10 + nt] = t.w;
            }
#pragma unroll
            for (int i = 0; i < 16; i++) acc16[i] = 0.f;
            if (v) {
                int beg = g_rowptr[n], end = g_rowptr[n + 1];
                for (int j = beg; j < end; j++) {
                    int s = g_srcs[j];
                    float w = wf[j];
                    const float4* sr = (const float4*)(in_state + s * 64) + cg * 4;
#pragma unroll
                    for (int q = 0; q < 4; q++) {
                        float4 t = sr[q];
                        acc16[q * 4 + 0] += w * t.x;
                        acc16[q * 4 + 1] += w * t.y;
                        acc16[q * 4 + 2] += w * t.z;
                        acc16[q * 4 + 3] += w * t.w;
                    }
                }
            }
#pragma unroll
            for (int i = 0; i < 16; i++) sA[(cg * 16 + i) * 10 + nt] = acc16[i];
        }
        __syncwarp();

        // ---- GraphConv: m = relu(agg@Wrel + brel + h@Wroot) ----
        u64 am[4][2];
#pragma unroll
        for (int p = 0; p < 4; p++) { am[p][0] = 0ull; am[p][1] = 0ull; }
#pragma unroll 2
        for (int k = 0; k < 64; k++) {
            float2 wr = *(const float2*)(sWrel + k * 64 + d0);
            float2 wo = *(const float2*)(sWroot + k * 64 + d0);
            u64 sr0 = splat2(wr.x), sr1 = splat2(wr.y);
            u64 so0 = splat2(wo.x), so1 = splat2(wo.y);
            const u64* ap = (const u64*)(sA + k * 10);
            const u64* hp = (const u64*)(sIn + k * 10);
#pragma unroll
            for (int p = 0; p < 4; p++) {
                u64 av = ap[p], hv = hp[p];
                am[p][0] = ffma2(av, sr0, am[p][0]);
                am[p][0] = ffma2(hv, so0, am[p][0]);
                am[p][1] = ffma2(av, sr1, am[p][1]);
                am[p][1] = ffma2(hv, so1, am[p][1]);
            }
        }
        __syncwarp();   // everyone done reading sA before it becomes sM
#pragma unroll
        for (int p = 0; p < 4; p++) {
            float2 c0 = unpk(am[p][0]), c1 = unpk(am[p][1]);
            float m00 = fmaxf(c0.x + br0, 0.f);
            float m10 = fmaxf(c0.y + br0, 0.f);
            float m01 = fmaxf(c1.x + br1, 0.f);
            float m11 = fmaxf(c1.y + br1, 0.f);
            *(u64*)(sA + d0 * 10 + 2 * p)       = pk(m00, m10);
            *(u64*)(sA + (d0 + 1) * 10 + 2 * p) = pk(m01, m11);
        }
        __syncwarp();

        // ---- GRU gates: gi = m@WihT, gh = h@WhhT ----
        u64 ai[4][6], ah[4][6];
#pragma unroll
        for (int p = 0; p < 4; p++)
#pragma unroll
            for (int g = 0; g < 6; g++) { ai[p][g] = 0ull; ah[p][g] = 0ull; }
#pragma unroll 1
        for (int k = 0; k < 64; k++) {
            const u64* mp = (const u64*)(sA + k * 10);
            const u64* hp = (const u64*)(sIn + k * 10);
            u64 mv[4], hv[4];
#pragma unroll
            for (int p = 0; p < 4; p++) { mv[p] = mp[p]; hv[p] = hp[p]; }
            const float* wi = sWihT + k * 192 + d0;
            const float* wh = sWhhT + k * 192 + d0;
#pragma unroll
            for (int g = 0; g < 3; g++) {
                float2 wiv = *(const float2*)(wi + 64 * g);
                float2 whv = *(const float2*)(wh + 64 * g);
                u64 si0 = splat2(wiv.x), si1 = splat2(wiv.y);
                u64 sh0 = splat2(whv.x), sh1 = splat2(whv.y);
#pragma unroll
                for (int p = 0; p < 4; p++) {
                    ai[p][2 * g]     = ffma2(mv[p], si0, ai[p][2 * g]);
                    ai[p][2 * g + 1] = ffma2(mv[p], si1, ai[p][2 * g + 1]);
                    ah[p][2 * g]     = ffma2(hv[p], sh0, ah[p][2 * g]);
                    ah[p][2 * g + 1] = ffma2(hv[p], sh1, ah[p][2 * g + 1]);
                }
            }
        }

        // ---- gates + blend + store ----
#pragma unroll
        for (int p = 0; p < 4; p++) {
            float2 h0 = unpk(*(const u64*)(sIn + d0 * 10 + 2 * p));
            float2 h1 = unpk(*(const u64*)(sIn + (d0 + 1) * 10 + 2 * p));
            float2 ir = unpk(ai[p][0]), irb = unpk(ai[p][1]);
            float2 iz = unpk(ai[p][2]), izb = unpk(ai[p][3]);
            float2 in0 = unpk(ai[p][4]), in1 = unpk(ai[p][5]);
            float2 hr = unpk(ah[p][0]), hrb = unpk(ah[p][1]);
            float2 hz = unpk(ah[p][2]), hzb = unpk(ah[p][3]);
            float2 hn0 = unpk(ah[p][4]), hn1 = unpk(ah[p][5]);

            // node a = n0 + 2p (lo halves)
            float ra0 = sigm(ir.x + bi_[0] + hr.x + bh_[0]);
            float ra1 = sigm(irb.x + bi_[1] + hrb.x + bh_[1]);
            float za0 = sigm(iz.x + bi_[2] + hz.x + bh_[2]);
            float za1 = sigm(izb.x + bi_[3] + hzb.x + bh_[3]);
            float na0 = tanhf(in0.x + bi_[4] + ra0 * (hn0.x + bh_[4]));
            float na1 = tanhf(in1.x + bi_[5] + ra1 * (hn1.x + bh_[5]));
            float oa0 = (1.f - za0) * na0 + za0 * h0.x;
            float oa1 = (1.f - za1) * na1 + za1 * h1.x;
            // node b = n0 + 2p + 1 (hi halves)
            float rb0 = sigm(ir.y + bi_[0] + hr.y + bh_[0]);
            float rb1 = sigm(irb.y + bi_[1] + hrb.y + bh_[1]);
            float zb0 = sigm(iz.y + bi_[2] + hz.y + bh_[2]);
            float zb1 = sigm(izb.y + bi_[3] + hzb.y + bh_[3]);
            float nb0 = tanhf(in0.y + bi_[4] + rb0 * (hn0.y + bh_[4]));
            float nb1 = tanhf(in1.y + bi_[5] + rb1 * (hn1.y + bh_[5]));
            float ob0 = (1.f - zb0) * nb0 + zb0 * h0.y;
            float ob1 = (1.f - zb1) * nb1 + zb1 * h1.y;

            int na = n0 + 2 * p, nb = na + 1;
            if (na < Nn) *(float2*)(out_state + na * 64 + d0) = make_float2(oa0, oa1);
            if (nb < Nn) *(float2*)(out_state + nb * 64 + d0) = make_float2(ob0, ob1);
        }
        __syncwarp();
    }
}

// ---------------- global mean pool ----------------
__global__ void k_pool(const float* __restrict__ feats, float* __restrict__ out) {
    int g = blockIdx.x, f = blockIdx.y, d = threadIdx.x;  // blockDim = 64
    int s = g_gstart[g], e = g_gstart[g + 1];
    const float* base = feats + f * Nn * Dd;
    float s0 = 0.f, s1 = 0.f, s2 = 0.f, s3 = 0.f;
    int i = s;
    for (; i + 3 < e; i += 4) {
        s0 += base[i * Dd + d];
        s1 += base[(i + 1) * Dd + d];
        s2 += base[(i + 2) * Dd + d];
        s3 += base[(i + 3) * Dd + d];
    }
    for (; i < e; i++) s0 += base[i * Dd + d];
    float sum = (s0 + s1) + (s2 + s3);
    int cnt = e - s;
    if (cnt < 1) cnt = 1;
    out[(f * Gg + g) * Dd + d] = sum / (float)cnt;
}

// ---------------- host ----------------
extern "C" void kernel_launch(void* const* d_in, const int* in_sizes, int n_in,
                              void* d_out, int out_size) {
    const float* x     = (const float*)d_in[0];
    const int*   ei    = (const int*)d_in[1];
    const float* att   = (const float*)d_in[2];
    const int*   batch = (const int*)d_in[3];
    const float* lin_W = (const float*)d_in[4];
    const float* lin_b = (const float*)d_in[5];
    const float* Wrel  = (const float*)d_in[6];
    const float* brel  = (const float*)d_in[7];
    const float* Wroot = (const float*)d_in[8];
    const float* Wih   = (const float*)d_in[9];
    const float* Whh   = (const float*)d_in[10];
    const float* bih   = (const float*)d_in[11];
    const float* bhh   = (const float*)d_in[12];

    float* out = (float*)d_out;
    float* feats = out + NFf * Gg * Dd;
    const int* srcp = ei;
    const int* dstp = ei + Ee;

    int sm = 148;
    cudaDeviceGetAttribute(&sm, cudaDevAttrMultiProcessorCount, 0);

    cudaFuncSetAttribute(k_layer, cudaFuncAttributeMaxDynamicSharedMemorySize, LAYER_SHM);
    cudaFuncSetAttribute(k_lin, cudaFuncAttributeMaxDynamicSharedMemorySize, LIN_SHM);

    void *pa, *pb, *pw;
    cudaGetSymbolAddress(&pa, g_stateA);
    cudaGetSymbolAddress(&pb, g_stateB);
    cudaGetSymbolAddress(&pw, g_wcsr);
    float* A = (float*)pa;
    float* B = (float*)pb;
    float* wcsr = (float*)pw;

    const int NB = (Nn + 1023) / 1024;

    k_zero<<<(Nn + 255) / 256, 256>>>();
    k_hist<<<(Ee + 255) / 256, 256>>>(dstp, batch);
    k_scan1<<<NB, 1024>>>();
    k_scan2<<<1, 32>>>(NB);
    k_scan3<<<NB, 1024>>>();
    k_scatter<<<(Ee + 255) / 256, 256>>>(srcp, dstp);
    k_sortseg<<<(Nn + 127) / 128, 128>>>();
    k_buildw<<<(Ee + 255) / 256, 256>>>(att);
    k_gscan<<<1, 32>>>();

    for (int f = 0; f < NFf; f++) {
        k_lin<<<sm, 384, LIN_SHM>>>(x, lin_W + f * Ff * Dd, lin_b + f * Dd, A);
        float* cur = A;
        for (int l = 0; l < NLl; l++) {
            float* nxt = (l == NLl - 1) ? (feats + f * Nn * Dd) : (cur == A ? B : A);
            int wl = f * NLl + l;
            k_layer<<<sm, 384, LAYER_SHM>>>(cur, nxt,
                                            Wrel + wl * Dd * Dd, brel + wl * Dd,
                                            Wroot + wl * Dd * Dd,
                                            Wih + f * 3 * Dd * Dd, Whh + f * 3 * Dd * Dd,
                                            bih + f * 3 * Dd, bhh + f * 3 * Dd,
                                            wcsr + f * Ee);
            cur = nxt;
        }
    }
    k_pool<<<dim3(Gg, NFf), 64>>>(feats, out);
}

// round 3
// speedup vs baseline: 1.9745x; 1.0168x over previous
#include <cuda_runtime.h>
#include <math.h>

typedef unsigned long long u64;
typedef unsigned int u32;

#define Nn 100000
#define Ee 1600000
#define Ff 128
#define NFf 4
#define Dd 64
#define NLl 3
#define Gg 128
#define NTILE 782   // ceil(Nn/128)

// ---------------- device scratch (no allocations allowed) ----------------
__device__ int   g_deg[Nn];
__device__ int   g_rowptr[Nn + 1];
__device__ int   g_fill[Nn];
__device__ int   g_bsums[256];
__device__ int   g_srcs[Ee];
__device__ int   g_eids[Ee];
__device__ float g_wcsr[NFf * Ee];
__device__ float g_stateA[NFf * Nn * Dd];
__device__ float g_stateB[NFf * Nn * Dd];
__device__ int   g_gcnt[Gg];
__device__ int   g_gstart[Gg + 1];

// ---------------- packed f32x2 helpers ----------------
__device__ __forceinline__ u64 ffma2(u64 a, u64 b, u64 c) {
    u64 d; asm("fma.rn.f32x2 %0,%1,%2,%3;" : "=l"(d) : "l"(a), "l"(b), "l"(c)); return d;
}
__device__ __forceinline__ u64 splat2(float v) {
    u64 d; u32 r = __float_as_uint(v);
    asm("mov.b64 %0,{%1,%2};" : "=l"(d) : "r"(r), "r"(r)); return d;
}
__device__ __forceinline__ float2 unpk(u64 v) {
    u32 lo, hi; asm("mov.b64 {%0,%1},%2;" : "=r"(lo), "=r"(hi) : "l"(v));
    return make_float2(__uint_as_float(lo), __uint_as_float(hi));
}
__device__ __forceinline__ u64 pk(float a, float b) {
    u64 d;
    asm("mov.b64 %0,{%1,%2};" : "=l"(d) : "r"(__float_as_uint(a)), "r"(__float_as_uint(b)));
    return d;
}
__device__ __forceinline__ float sigm(float v) { return 1.f / (1.f + __expf(-v)); }
__device__ __forceinline__ float tanh_f(float v) { return 2.f / (1.f + __expf(-2.f * v)) - 1.f; }

// ---------------- CSR build ----------------
__global__ void k_zero() {
    int i = blockIdx.x * blockDim.x + threadIdx.x;
    if (i < Nn) g_deg[i] = 0;
    if (i < Gg) g_gcnt[i] = 0;
}

__global__ void k_hist(const int* __restrict__ dst, const int* __restrict__ batch) {
    int i = blockIdx.x * blockDim.x + threadIdx.x;
    if (i < Ee) atomicAdd(&g_deg[dst[i]], 1);
    if (i < Nn) atomicAdd(&g_gcnt[batch[i]], 1);
}

__global__ void k_scan1() {
    __shared__ int tmp[1024];
    int i = blockIdx.x * 1024 + threadIdx.x;
    int v = (i < Nn) ? g_deg[i] : 0;
    tmp[threadIdx.x] = v;
    __syncthreads();
    for (int off = 1; off < 1024; off <<= 1) {
        int t = 0;
        if (threadIdx.x >= off) t = tmp[threadIdx.x - off];
        __syncthreads();
        if (threadIdx.x >= off) tmp[threadIdx.x] += t;
        __syncthreads();
    }
    if (i < Nn) g_rowptr[i + 1] = tmp[threadIdx.x];
    if (threadIdx.x == 1023) g_bsums[blockIdx.x] = tmp[1023];
}

__global__ void k_scan2(int nb) {
    if (threadIdx.x == 0 && blockIdx.x == 0) {
        int run = 0;
        for (int b = 0; b < nb; b++) { int v = g_bsums[b]; g_bsums[b] = run; run += v; }
    }
}

__global__ void k_scan3() {
    int i = blockIdx.x * 1024 + threadIdx.x;
    if (i < Nn) {
        int v = g_rowptr[i + 1] + g_bsums[blockIdx.x];
        g_rowptr[i + 1] = v;
        if (i + 1 < Nn) g_fill[i + 1] = v;
    }
    if (i == 0) { g_rowptr[0] = 0; g_fill[0] = 0; }
}

__global__ void k_scatter(const int* __restrict__ src, const int* __restrict__ dst) {
    int e = blockIdx.x * blockDim.x + threadIdx.x;
    if (e < Ee) {
        int d = dst[e];
        int p = atomicAdd(&g_fill[d], 1);
        g_srcs[p] = src[e];
        g_eids[p] = e;
    }
}

__global__ void k_sortseg() {
    int n = blockIdx.x * blockDim.x + threadIdx.x;
    if (n >= Nn) return;
    int b = g_rowptr[n], e = g_rowptr[n + 1];
    for (int i = b + 1; i < e; i++) {
        int ke = g_eids[i], ks = g_srcs[i];
        int j = i - 1;
        while (j >= b && g_eids[j] > ke) {
            g_eids[j + 1] = g_eids[j];
            g_srcs[j + 1] = g_srcs[j];
            j--;
        }
        g_eids[j + 1] = ke;
        g_srcs[j + 1] = ks;
    }
}

__global__ void k_buildw(const float* __restrict__ att) {
    int j = blockIdx.x * blockDim.x + threadIdx.x;
    if (j < Ee) {
        int e = g_eids[j];
#pragma unroll
        for (int f = 0; f < NFf; f++) g_wcsr[f * Ee + j] = att[f * Ee + e];
    }
}

__global__ void k_gscan() {
    if (threadIdx.x == 0 && blockIdx.x == 0) {
        int run = 0;
        for (int g = 0; g < Gg; g++) { g_gstart[g] = run; run += g_gcnt[g]; }
        g_gstart[Gg] = run;
    }
}

// ---------------- lin (all factors, 8 nodes/warp, 16 warps) ----------------
#define LIN_SHM ((8192 + 64 + 16 * 1280) * 4)
__global__ __launch_bounds__(512, 1) void k_lin(const float* __restrict__ x,
                                                const float* __restrict__ W_all,
                                                const float* __restrict__ b_all,
                                                float* __restrict__ out_base) {
    extern __shared__ float sh[];
    float* sW = sh;            // 8192 [k][d]
    float* sb = sW + 8192;     // 64
    float* sX = sb + 64;       // 16 * 1280
    int f = blockIdx.x & 3;
    int fslot = blockIdx.x >> 2;
    int nslot = gridDim.x >> 2;
    const float* W = W_all + f * Ff * Dd;
    const float* b = b_all + f * Dd;
    float* out = out_base + f * Nn * Dd;

    int tid = threadIdx.x;
    for (int i = tid; i < 8192; i += 512) sW[i] = W[i];
    if (tid < 64) sb[tid] = b[tid];
    __syncthreads();
    int warp = tid >> 5, lane = tid & 31;
    int d0 = 2 * lane;
    int nt = lane >> 2, cg = lane & 3;
    float* sXw = sX + warp * 1280;
    float bc0 = sb[d0], bc1 = sb[d0 + 1];

    for (int t = fslot; t < NTILE; t += nslot) {
        int n0 = t * 128 + warp * 8;
        if (n0 >= Nn) continue;
        {
            int n = n0 + nt;
            bool v = n < Nn;
            const float4* xr = (const float4*)(x + (v ? n : 0) * Ff) + cg * 8;
#pragma unroll
            for (int q = 0; q < 8; q++) {
                float4 tv = v ? xr[q] : make_float4(0, 0, 0, 0);
                int c = cg * 32 + q * 4;
                sXw[(c + 0) * 10 + nt] = tv.x;
                sXw[(c + 1) * 10 + nt] = tv.y;
                sXw[(c + 2) * 10 + nt] = tv.z;
                sXw[(c + 3) * 10 + nt] = tv.w;
            }
        }
        __syncwarp();
        u64 acc[4][2];
#pragma unroll
        for (int p = 0; p < 4; p++) { acc[p][0] = 0ull; acc[p][1] = 0ull; }
#pragma unroll 4
        for (int k = 0; k < Ff; k++) {
            float2 w = *(const float2*)(sW + k * 64 + d0);
            u64 sw0 = splat2(w.x), sw1 = splat2(w.y);
            const u64* xp = (const u64*)(sXw + k * 10);
#pragma unroll
            for (int p = 0; p < 4; p++) {
                u64 xv = xp[p];
                acc[p][0] = ffma2(xv, sw0, acc[p][0]);
                acc[p][1] = ffma2(xv, sw1, acc[p][1]);
            }
        }
#pragma unroll
        for (int p = 0; p < 4; p++) {
            float2 a0 = unpk(acc[p][0]), a1 = unpk(acc[p][1]);
            int na = n0 + 2 * p, nb = na + 1;
            if (na < Nn) *(float2*)(out + na * 64 + d0) = make_float2(a0.x + bc0, a1.x + bc1);
            if (nb < Nn) *(float2*)(out + nb * 64 + d0) = make_float2(a0.y + bc0, a1.y + bc1);
        }
        __syncwarp();
    }
}

// ---------------- fused layer (all factors, 8 nodes/warp, 16 warps) ----------------
#define LAYER_SHM ((4096 * 2 + 12288 * 2 + 16 * 1280) * 4)
__global__ __launch_bounds__(512, 1) void k_layer(const float* __restrict__ in_base,
                                                  float* __restrict__ out_base,
                                                  int layer,
                                                  const float* __restrict__ Wrel_all,
                                                  const float* __restrict__ brel_all,
                                                  const float* __restrict__ Wroot_all,
                                                  const float* __restrict__ Wih_all,
                                                  const float* __restrict__ Whh_all,
                                                  const float* __restrict__ bih_all,
                                                  const float* __restrict__ bhh_all) {
    extern __shared__ float sh[];
    float* sWrel  = sh;                  // 4096  [k][d]
    float* sWroot = sWrel + 4096;        // 4096
    float* sWihT  = sWroot + 4096;       // 12288 [k][j]
    float* sWhhT  = sWihT + 12288;       // 12288
    float* sStage = sWhhT + 12288;       // 16 warps * 1280

    int f = blockIdx.x & 3;
    int fslot = blockIdx.x >> 2;
    int nslot = gridDim.x >> 2;
    int wl = f * NLl + layer;
    const float* in_state = in_base + f * Nn * Dd;
    float* out_state = out_base + f * Nn * Dd;
    const float* Wrel  = Wrel_all + wl * Dd * Dd;
    const float* Wroot = Wroot_all + wl * Dd * Dd;
    const float* brel  = brel_all + wl * Dd;
    const float* Wih   = Wih_all + f * 3 * Dd * Dd;
    const float* Whh   = Whh_all + f * 3 * Dd * Dd;
    const float* bih   = bih_all + f * 3 * Dd;
    const float* bhh   = bhh_all + f * 3 * Dd;
    const float* wf    = g_wcsr + f * Ee;

    int tid = threadIdx.x;
    for (int i = tid; i < 4096; i += 512) { sWrel[i] = Wrel[i]; sWroot[i] = Wroot[i]; }
    for (int i = tid; i < 12288; i += 512) {
        int j = i >> 6, k = i & 63;
        sWihT[k * 192 + j] = Wih[i];
        sWhhT[k * 192 + j] = Whh[i];
    }
    __syncthreads();

    int warp = tid >> 5, lane = tid & 31;
    int d0 = 2 * lane;
    int nt = lane >> 2, cg = lane & 3;
    float* sIn = sStage + warp * 1280;   // [col][10]
    float* sA  = sIn + 640;              // agg, then m

    float br0 = brel[d0], br1 = brel[d0 + 1];
    float bi_[6], bh_[6];
#pragma unroll
    for (int g = 0; g < 3; g++) {
        bi_[2 * g] = bih[64 * g + d0]; bi_[2 * g + 1] = bih[64 * g + d0 + 1];
        bh_[2 * g] = bhh[64 * g + d0]; bh_[2 * g + 1] = bhh[64 * g + d0 + 1];
    }

    for (int t = fslot; t < NTILE; t += nslot) {
        int n0 = t * 128 + warp * 8;
        if (n0 >= Nn) continue;

        // ---- stage h + edge aggregation, transposed [col][node] ----
        {
            int n = n0 + nt;
            bool v = n < Nn;
            const float4* xr = (const float4*)(in_state + (v ? n : 0) * 64) + cg * 4;
            float acc16[16];
#pragma unroll
            for (int q = 0; q < 4; q++) {
                float4 tv = v ? xr[q] : make_float4(0, 0, 0, 0);
                int c = cg * 16 + q * 4;
                sIn[(c + 0) * 10 + nt] = tv.x;
                sIn[(c + 1) * 10 + nt] = tv.y;
                sIn[(c + 2) * 10 + nt] = tv.z;
                sIn[(c + 3) * 10 + nt] = tv.w;
            }
#pragma unroll
            for (int i = 0; i < 16; i++) acc16[i] = 0.f;
            if (v) {
                int beg = g_rowptr[n], end = g_rowptr[n + 1];
                for (int j = beg; j < end; j++) {
                    int s = g_srcs[j];
                    float w = wf[j];
                    const float4* sr = (const float4*)(in_state + s * 64) + cg * 4;
#pragma unroll
                    for (int q = 0; q < 4; q++) {
                        float4 tv = sr[q];
                        acc16[q * 4 + 0] += w * tv.x;
                        acc16[q * 4 + 1] += w * tv.y;
                        acc16[q * 4 + 2] += w * tv.z;
                        acc16[q * 4 + 3] += w * tv.w;
                    }
                }
            }
#pragma unroll
            for (int i = 0; i < 16; i++) sA[(cg * 16 + i) * 10 + nt] = acc16[i];
        }
        __syncwarp();

        // ---- GraphConv: m = relu(agg@Wrel + brel + h@Wroot) ----
        {
            u64 am[4][2];
#pragma unroll
            for (int p = 0; p < 4; p++) { am[p][0] = 0ull; am[p][1] = 0ull; }
#pragma unroll 2
            for (int k = 0; k < 64; k++) {
                float2 wr = *(const float2*)(sWrel + k * 64 + d0);
                float2 wo = *(const float2*)(sWroot + k * 64 + d0);
                u64 sr0 = splat2(wr.x), sr1 = splat2(wr.y);
                u64 so0 = splat2(wo.x), so1 = splat2(wo.y);
                const u64* ap = (const u64*)(sA + k * 10);
                const u64* hp = (const u64*)(sIn + k * 10);
#pragma unroll
                for (int p = 0; p < 4; p++) {
                    u64 av = ap[p], hv = hp[p];
                    am[p][0] = ffma2(av, sr0, am[p][0]);
                    am[p][0] = ffma2(hv, so0, am[p][0]);
                    am[p][1] = ffma2(av, sr1, am[p][1]);
                    am[p][1] = ffma2(hv, so1, am[p][1]);
                }
            }
            __syncwarp();   // done reading sA (agg) before overwrite with m
#pragma unroll
            for (int p = 0; p < 4; p++) {
                float2 c0 = unpk(am[p][0]), c1 = unpk(am[p][1]);
                float m00 = fmaxf(c0.x + br0, 0.f);
                float m10 = fmaxf(c0.y + br0, 0.f);
                float m01 = fmaxf(c1.x + br1, 0.f);
                float m11 = fmaxf(c1.y + br1, 0.f);
                *(u64*)(sA + d0 * 10 + 2 * p)       = pk(m00, m10);
                *(u64*)(sA + (d0 + 1) * 10 + 2 * p) = pk(m01, m11);
            }
        }
        __syncwarp();

        // ---- GRU pass 1: r and z gates ----
        u64 rp[8], zp[8];
        {
            u64 arz[4][4], hrz[4][4];
#pragma unroll
            for (int p = 0; p < 4; p++)
#pragma unroll
                for (int g = 0; g < 4; g++) { arz[p][g] = 0ull; hrz[p][g] = 0ull; }
#pragma unroll 1
            for (int k = 0; k < 64; k++) {
                const u64* mp = (const u64*)(sA + k * 10);
                const u64* hp = (const u64*)(sIn + k * 10);
                const float* wi = sWihT + k * 192 + d0;
                const float* wh = sWhhT + k * 192 + d0;
                float2 wir = *(const float2*)(wi);
                float2 wiz = *(const float2*)(wi + 64);
                float2 whr = *(const float2*)(wh);
                float2 whz = *(const float2*)(wh + 64);
                u64 sir0 = splat2(wir.x), sir1 = splat2(wir.y);
                u64 siz0 = splat2(wiz.x), siz1 = splat2(wiz.y);
                u64 shr0 = splat2(whr.x), shr1 = splat2(whr.y);
                u64 shz0 = splat2(whz.x), shz1 = splat2(whz.y);
#pragma unroll
                for (int p = 0; p < 4; p++) {
                    u64 mv = mp[p], hv = hp[p];
                    arz[p][0] = ffma2(mv, sir0, arz[p][0]);
                    arz[p][1] = ffma2(mv, sir1, arz[p][1]);
                    arz[p][2] = ffma2(mv, siz0, arz[p][2]);
                    arz[p][3] = ffma2(mv, siz1, arz[p][3]);
                    hrz[p][0] = ffma2(hv, shr0, hrz[p][0]);
                    hrz[p][1] = ffma2(hv, shr1, hrz[p][1]);
                    hrz[p][2] = ffma2(hv, shz0, hrz[p][2]);
                    hrz[p][3] = ffma2(hv, shz1, hrz[p][3]);
                }
            }
#pragma unroll
            for (int p = 0; p < 4; p++) {
                float2 vir0 = unpk(arz[p][0]), vir1 = unpk(arz[p][1]);
                float2 viz0 = unpk(arz[p][2]), viz1 = unpk(arz[p][3]);
                float2 vhr0 = unpk(hrz[p][0]), vhr1 = unpk(hrz[p][1]);
                float2 vhz0 = unpk(hrz[p][2]), vhz1 = unpk(hrz[p][3]);
                float ra0 = sigm(vir0.x + bi_[0] + vhr0.x + bh_[0]);
                float rb0 = sigm(vir0.y + bi_[0] + vhr0.y + bh_[0]);
                float ra1 = sigm(vir1.x + bi_[1] + vhr1.x + bh_[1]);
                float rb1 = sigm(vir1.y + bi_[1] + vhr1.y + bh_[1]);
                float za0 = sigm(viz0.x + bi_[2] + vhz0.x + bh_[2]);
                float zb0 = sigm(viz0.y + bi_[2] + vhz0.y + bh_[2]);
                float za1 = sigm(viz1.x + bi_[3] + vhz1.x + bh_[3]);
                float zb1 = sigm(viz1.y + bi_[3] + vhz1.y + bh_[3]);
                rp[2 * p] = pk(ra0, rb0); rp[2 * p + 1] = pk(ra1, rb1);
                zp[2 * p] = pk(za0, zb0); zp[2 * p + 1] = pk(za1, zb1);
            }
        }

        // ---- GRU pass 2: n gate + blend + store ----
        {
            u64 an_[4][2], hn_[4][2];
#pragma unroll
            for (int p = 0; p < 4; p++) { an_[p][0] = 0ull; an_[p][1] = 0ull; hn_[p][0] = 0ull; hn_[p][1] = 0ull; }
#pragma unroll 2
            for (int k = 0; k < 64; k++) {
                const u64* mp = (const u64*)(sA + k * 10);
                const u64* hp = (const u64*)(sIn + k * 10);
                float2 win = *(const float2*)(sWihT + k * 192 + 128 + d0);
                float2 whn = *(const float2*)(sWhhT + k * 192 + 128 + d0);
                u64 sin0 = splat2(win.x), sin1 = splat2(win.y);
                u64 shn0 = splat2(whn.x), shn1 = splat2(whn.y);
#pragma unroll
                for (int p = 0; p < 4; p++) {
                    u64 mv = mp[p], hv = hp[p];
                    an_[p][0] = ffma2(mv, sin0, an_[p][0]);
                    an_[p][1] = ffma2(mv, sin1, an_[p][1]);
                    hn_[p][0] = ffma2(hv, shn0, hn_[p][0]);
                    hn_[p][1] = ffma2(hv, shn1, hn_[p][1]);
                }
            }
#pragma unroll
            for (int p = 0; p < 4; p++) {
                float2 vin0 = unpk(an_[p][0]), vin1 = unpk(an_[p][1]);
                float2 vhn0 = unpk(hn_[p][0]), vhn1 = unpk(hn_[p][1]);
                float2 r0 = unpk(rp[2 * p]), r1 = unpk(rp[2 * p + 1]);
                float2 z0 = unpk(zp[2 * p]), z1 = unpk(zp[2 * p + 1]);
                float2 h0 = unpk(*(const u64*)(sIn + d0 * 10 + 2 * p));
                float2 h1 = unpk(*(const u64*)(sIn + (d0 + 1) * 10 + 2 * p));
                float na0 = tanh_f(vin0.x + bi_[4] + r0.x * (vhn0.x + bh_[4]));
                float nb0 = tanh_f(vin0.y + bi_[4] + r0.y * (vhn0.y + bh_[4]));
                float na1 = tanh_f(vin1.x + bi_[5] + r1.x * (vhn1.x + bh_[5]));
                float nb1 = tanh_f(vin1.y + bi_[5] + r1.y * (vhn1.y + bh_[5]));
                float oa0 = (1.f - z0.x) * na0 + z0.x * h0.x;
                float ob0 = (1.f - z0.y) * nb0 + z0.y * h0.y;
                float oa1 = (1.f - z1.x) * na1 + z1.x * h1.x;
                float ob1 = (1.f - z1.y) * nb1 + z1.y * h1.y;
                int na = n0 + 2 * p, nb = na + 1;
                if (na < Nn) *(float2*)(out_state + na * 64 + d0) = make_float2(oa0, oa1);
                if (nb < Nn) *(float2*)(out_state + nb * 64 + d0) = make_float2(ob0, ob1);
            }
        }
        __syncwarp();
    }
}

// ---------------- global mean pool ----------------
__global__ void k_pool(const float* __restrict__ feats, float* __restrict__ out) {
    int g = blockIdx.x, f = blockIdx.y, d = threadIdx.x;  // blockDim = 64
    int s = g_gstart[g], e = g_gstart[g + 1];
    const float* base = feats + f * Nn * Dd;
    float s0 = 0.f, s1 = 0.f, s2 = 0.f, s3 = 0.f;
    int i = s;
    for (; i + 3 < e; i += 4) {
        s0 += base[i * Dd + d];
        s1 += base[(i + 1) * Dd + d];
        s2 += base[(i + 2) * Dd + d];
        s3 += base[(i + 3) * Dd + d];
    }
    for (; i < e; i++) s0 += base[i * Dd + d];
    float sum = (s0 + s1) + (s2 + s3);
    int cnt = e - s;
    if (cnt < 1) cnt = 1;
    out[(f * Gg + g) * Dd + d] = sum / (float)cnt;
}

// ---------------- host ----------------
extern "C" void kernel_launch(void* const* d_in, const int* in_sizes, int n_in,
                              void* d_out, int out_size) {
    const float* x     = (const float*)d_in[0];
    const int*   ei    = (const int*)d_in[1];
    const float* att   = (const float*)d_in[2];
    const int*   batch = (const int*)d_in[3];
    const float* lin_W = (const float*)d_in[4];
    const float* lin_b = (const float*)d_in[5];
    const float* Wrel  = (const float*)d_in[6];
    const float* brel  = (const float*)d_in[7];
    const float* Wroot = (const float*)d_in[8];
    const float* Wih   = (const float*)d_in[9];
    const float* Whh   = (const float*)d_in[10];
    const float* bih   = (const float*)d_in[11];
    const float* bhh   = (const float*)d_in[12];

    float* out = (float*)d_out;
    float* feats = out + NFf * Gg * Dd;
    const int* srcp = ei;
    const int* dstp = ei + Ee;

    int sm = 148;
    cudaDeviceGetAttribute(&sm, cudaDevAttrMultiProcessorCount, 0);
    int grid = (sm / 4) * 4;
    if (grid < 4) grid = 4;

    cudaFuncSetAttribute(k_layer, cudaFuncAttributeMaxDynamicSharedMemorySize, LAYER_SHM);
    cudaFuncSetAttribute(k_lin, cudaFuncAttributeMaxDynamicSharedMemorySize, LIN_SHM);

    void *pa, *pb;
    cudaGetSymbolAddress(&pa, g_stateA);
    cudaGetSymbolAddress(&pb, g_stateB);
    float* A = (float*)pa;
    float* B = (float*)pb;

    const int NB = (Nn + 1023) / 1024;

    k_zero<<<(Nn + 255) / 256, 256>>>();
    k_hist<<<(Ee + 255) / 256, 256>>>(dstp, batch);
    k_scan1<<<NB, 1024>>>();
    k_scan2<<<1, 32>>>(NB);
    k_scan3<<<NB, 1024>>>();
    k_scatter<<<(Ee + 255) / 256, 256>>>(srcp, dstp);
    k_sortseg<<<(Nn + 127) / 128, 128>>>();
    k_buildw<<<(Ee + 255) / 256, 256>>>(att);
    k_gscan<<<1, 32>>>();

    k_lin<<<grid, 512, LIN_SHM>>>(x, lin_W, lin_b, A);
    k_layer<<<grid, 512, LAYER_SHM>>>(A, B, 0, Wrel, brel, Wroot, Wih, Whh, bih, bhh);
    k_layer<<<grid, 512, LAYER_SHM>>>(B, A, 1, Wrel, brel, Wroot, Wih, Whh, bih, bhh);
    k_layer<<<grid, 512, LAYER_SHM>>>(A, feats, 2, Wrel, brel, Wroot, Wih, Whh, bih, bhh);
    k_pool<<<dim3(Gg, NFf), 64>>>(feats, out);
}